// round 10
// baseline (speedup 1.0000x reference)
#include <cuda_runtime.h>
#include <math.h>

#define B 64
#define N 8192
#define M 128
#define EPS 1e-16f
#define EPS_COS 1e-8f

// ---------------- scratch (no allocation allowed) ----------------
__device__ float g_cos[B * N];            // 2 MB: cos, reused as addr scratch
__device__ float g_w[B * N];              // 2 MB: final weights
__device__ float g_pr[B * 128 * M];       // 4 MB: partial r [B][128][M]
__device__ unsigned int g_cnt_w[B];       // write-completion tickets
__device__ unsigned int g_flag[B];        // per-batch "w ready" flags

// ============ kernel 1: cosine similarity (pure) ============
// grid (N/64, B), 256 threads. k-side hoisted, 8 lanes per row.
#define CROWS 64
__global__ __launch_bounds__(256) void cos_kernel(
    const float* __restrict__ mem, const float* __restrict__ k)
{
    __shared__ float4 ks[32];
    __shared__ float s_invnk;
    int b = blockIdx.y;
    int tid = threadIdx.x;

    if (tid < 32) {
        float4 k4 = reinterpret_cast<const float4*>(k + b * M)[tid];
        k4.x += EPS; k4.y += EPS; k4.z += EPS; k4.w += EPS;
        ks[tid] = k4;
        float nk2 = k4.x * k4.x + k4.y * k4.y + k4.z * k4.z + k4.w * k4.w;
        #pragma unroll
        for (int s = 16; s > 0; s >>= 1) nk2 += __shfl_xor_sync(0xffffffffu, nk2, s);
        if (tid == 0) s_invnk = 1.f / fmaxf(sqrtf(nk2), EPS_COS);
    }
    __syncthreads();

    int warp = tid >> 5, lane = tid & 31;
    int sub = lane >> 3, lane8 = lane & 7;
    int n0 = blockIdx.x * CROWS;
    float invnk = s_invnk;

    #pragma unroll
    for (int iter = 0; iter < 2; ++iter) {
        int row = n0 + iter * 32 + warp * 4 + sub;
        const float4* mp = reinterpret_cast<const float4*>(
            mem + ((size_t)b * N + row) * M);

        float dot = 0.f, nm2 = 0.f;
        #pragma unroll
        for (int j = 0; j < 4; ++j) {
            float4 m4 = __ldcs(mp + lane8 + j * 8);
            float4 k4 = ks[lane8 + j * 8];
            float mx = m4.x + EPS, my = m4.y + EPS, mz = m4.z + EPS, mw = m4.w + EPS;
            dot += mx * k4.x + my * k4.y + mz * k4.z + mw * k4.w;
            nm2 += mx * mx + my * my + mz * mz + mw * mw;
        }
        #pragma unroll
        for (int s = 4; s > 0; s >>= 1) {
            dot += __shfl_xor_sync(0xffffffffu, dot, s);
            nm2 += __shfl_xor_sync(0xffffffffu, nm2, s);
        }
        if (lane8 == 0) {
            float nm = fmaxf(sqrtf(nm2), EPS_COS);
            g_cos[(size_t)b * N + row] = dot * invnk / nm;
        }
    }
}

// ============ kernel 2: addr (x==128) + write with prefetch (x<128) ========
// grid (129, B), 256 threads. Addr block publishes flag[b]; write blocks
// prefetch their memory tile into regs before spinning -> HBM stays busy.
#define ROWS_PER_BLK 64
__global__ __launch_bounds__(256) void addr_write_kernel(
    const float* __restrict__ mem,
    const float* __restrict__ beta, const float* __restrict__ g,
    const float* __restrict__ s, const float* __restrict__ gamma,
    const float* __restrict__ w_prev, const float* __restrict__ e,
    const float* __restrict__ a, float* __restrict__ newmem,
    float* __restrict__ r_out)
{
    __shared__ float4 sd[256];
    __shared__ float red[8];
    __shared__ bool is_last;

    int b = blockIdx.y;
    int tid = threadIdx.x;
    int warp = tid >> 5, lane = tid & 31;

    if (blockIdx.x == 128) {
        // ---------------- addr block (one per batch) ----------------
        float betav = beta[b], gv = g[b], gammav = gamma[b];
        float s0 = s[b * 3 + 0], s1 = s[b * 3 + 1], s2 = s[b * 3 + 2];
        float* cw = g_cos + (size_t)b * N;     // in-place scratch (L2-hot)
        float* wo = g_w + (size_t)b * N;
        const float* wpv = w_prev + (size_t)b * N;

        // pass 1: ev = exp(beta*cos) (|beta*cos| <= 5 -> no max shift), sum
        float sum = 0.f;
        #pragma unroll
        for (int j = 0; j < N / 256; ++j) {
            int i = tid + j * 256;
            float ev = __expf(betav * cw[i]);
            cw[i] = ev;
            sum += ev;
        }
        #pragma unroll
        for (int t = 16; t > 0; t >>= 1) sum += __shfl_xor_sync(0xffffffffu, sum, t);
        if (lane == 0) red[warp] = sum;
        __syncthreads();
        float bsum = 0.f;
        #pragma unroll
        for (int w = 0; w < 8; ++w) bsum += red[w];
        float inv = 1.f / bsum;

        // pass 2: wg = g*wc + (1-g)*w_prev (in place)
        #pragma unroll
        for (int j = 0; j < N / 256; ++j) {
            int i = tid + j * 256;
            cw[i] = gv * (cw[i] * inv) + (1.f - gv) * wpv[i];
        }
        __syncthreads();

        // pass 3: circular shift + sharpen -> g_w, sum
        float sum2 = 0.f;
        #pragma unroll
        for (int j = 0; j < N / 256; ++j) {
            int i = tid + j * 256;
            int im1 = (i == 0) ? (N - 1) : (i - 1);
            int ip1 = (i == N - 1) ? 0 : (i + 1);
            float wh = s0 * cw[im1] + s1 * cw[i] + s2 * cw[ip1];
            float ww = __expf(gammav * __logf(wh));   // wh > 0 always
            wo[i] = ww;
            sum2 += ww;
        }
        #pragma unroll
        for (int t = 16; t > 0; t >>= 1) sum2 += __shfl_xor_sync(0xffffffffu, sum2, t);
        __syncthreads();
        if (lane == 0) red[warp] = sum2;
        __syncthreads();
        float bsum2 = 0.f;
        #pragma unroll
        for (int w = 0; w < 8; ++w) bsum2 += red[w];
        float inv2 = 1.f / (bsum2 + EPS);

        // pass 4: scale
        #pragma unroll
        for (int j = 0; j < N / 256; ++j) {
            int i = tid + j * 256;
            wo[i] *= inv2;
        }

        __threadfence();
        if (tid == 0) atomicExch(&g_flag[b], 1u);
        return;
    }

    // ---------------- write block ----------------
    int blk = blockIdx.x;              // 0..127
    int m4 = tid & 31;
    int grp = tid >> 5;

    int n0 = blk * ROWS_PER_BLK;
    size_t base = ((size_t)b * N + n0) * M;
    const float4* mp = reinterpret_cast<const float4*>(mem + base);
    float4* op = reinterpret_cast<float4*>(newmem + base);
    const float* wp = g_w + (size_t)b * N + n0;

    // prefetch the whole tile (independent of w) -> loads in flight while
    // this batch's addr block computes
    float4 mv[8];
    #pragma unroll
    for (int it = 0; it < 8; ++it) {
        mv[it] = __ldcs(mp + (it * 8 + grp) * 32 + m4);
    }
    const float4 e4 = reinterpret_cast<const float4*>(e + b * M)[m4];
    const float4 a4 = reinterpret_cast<const float4*>(a + b * M)[m4];

    // wait for this batch's weights
    if (tid == 0) {
        while (atomicAdd(&g_flag[b], 0u) == 0u) __nanosleep(64);
    }
    __syncthreads();
    __threadfence();   // acquire: order g_w reads after flag observation

    float4 racc = make_float4(0.f, 0.f, 0.f, 0.f);
    #pragma unroll
    for (int it = 0; it < 8; ++it) {
        int row = it * 8 + grp;
        float wv = __ldg(wp + row);
        float4 m = mv[it];
        float4 o;
        o.x = m.x * (1.f - wv * e4.x) + wv * a4.x;
        o.y = m.y * (1.f - wv * e4.y) + wv * a4.y;
        o.z = m.z * (1.f - wv * e4.z) + wv * a4.z;
        o.w = m.w * (1.f - wv * e4.w) + wv * a4.w;
        __stcs(op + row * 32 + m4, o);
        racc.x += wv * m.x;
        racc.y += wv * m.y;
        racc.z += wv * m.z;
        racc.w += wv * m.w;
    }

    sd[tid] = racc;
    __syncthreads();
    #pragma unroll
    for (int st = 4; st > 0; st >>= 1) {
        if (grp < st) {
            float4 o = sd[tid + st * 32];
            sd[tid].x += o.x; sd[tid].y += o.y; sd[tid].z += o.z; sd[tid].w += o.w;
        }
        __syncthreads();
    }
    if (grp == 0) {
        reinterpret_cast<float4*>(g_pr + ((size_t)b * 128 + blk) * M)[m4] = sd[tid];
    }

    // ticket: last write block of this batch reduces the partials (L2-hot)
    __threadfence();
    if (tid == 0) {
        unsigned int v = atomicAdd(&g_cnt_w[b], 1u);
        is_last = (v == 127u);
        if (is_last) g_cnt_w[b] = 0;   // self-reset for graph replay
    }
    __syncthreads();
    if (!is_last) return;

    float4 acc = make_float4(0.f, 0.f, 0.f, 0.f);
    const float4* pp = reinterpret_cast<const float4*>(g_pr + (size_t)b * 128 * M);
    #pragma unroll
    for (int j = 0; j < 16; ++j) {
        float4 v = pp[(grp + j * 8) * 32 + m4];
        acc.x += v.x; acc.y += v.y; acc.z += v.z; acc.w += v.w;
    }
    __syncthreads();
    sd[tid] = acc;
    __syncthreads();
    #pragma unroll
    for (int st = 4; st > 0; st >>= 1) {
        if (grp < st) {
            float4 o = sd[tid + st * 32];
            sd[tid].x += o.x; sd[tid].y += o.y; sd[tid].z += o.z; sd[tid].w += o.w;
        }
        __syncthreads();
    }
    if (grp == 0) {
        reinterpret_cast<float4*>(r_out + b * M)[m4] = sd[tid];
    }
    // reset flag for next graph replay (all consumers already passed it)
    if (tid == 0) atomicExch(&g_flag[b], 0u);
}

// ---------------- launch ----------------
extern "C" void kernel_launch(void* const* d_in, const int* in_sizes, int n_in,
                              void* d_out, int out_size) {
    const float* memory = (const float*)d_in[0];
    const float* k      = (const float*)d_in[1];
    const float* beta   = (const float*)d_in[2];
    const float* g      = (const float*)d_in[3];
    const float* s      = (const float*)d_in[4];
    const float* gamma  = (const float*)d_in[5];
    const float* w_prev = (const float*)d_in[6];
    const float* e      = (const float*)d_in[7];
    const float* a      = (const float*)d_in[8];

    float* r_out  = (float*)d_out;            // [B, M]
    float* nm_out = (float*)d_out + B * M;    // [B, N, M]

    // kernel 1: pure cos
    dim3 grid1(N / CROWS, B);
    cos_kernel<<<grid1, 256>>>(memory, k);

    // kernel 2: addr (x==128) + write with register prefetch
    dim3 grid2(129, B);
    addr_write_kernel<<<grid2, 256>>>(memory, beta, g, s, gamma,
                                      w_prev, e, a, nm_out, r_out);
}

// round 11
// speedup vs baseline: 1.3222x; 1.3222x over previous
#include <cuda_runtime.h>
#include <math.h>

#define B 64
#define N 8192
#define M 128
#define EPS 1e-16f
#define EPS_COS 1e-8f

// ---------------- scratch (no allocation allowed) ----------------
__device__ float g_cos[B * N];            // 2 MB: cos, reused as addr scratch
__device__ float g_w[B * N];              // 2 MB: final weights
__device__ float g_pr[B * 128 * M];       // 4 MB: partial r [B][128][M]
__device__ unsigned int g_cnt_c[B];       // cos-completion tickets
__device__ unsigned int g_cnt_w[B];       // write-completion tickets
__device__ unsigned int g_flag[B];        // per-batch "w ready" flags

#define CROWS 64                          // rows per cos block (128 blocks/batch)
#define ROWS_PER_BLK 64                   // rows per write block (128 blocks/batch)

// bid layout: bid = b*256 + j ; j<128 cos, j>=128 write.
// Within a batch, all producers (cos+addr) have lower bids than all consumers.
__global__ __launch_bounds__(256) void ntm_kernel(
    const float* __restrict__ mem, const float* __restrict__ k,
    const float* __restrict__ beta, const float* __restrict__ g,
    const float* __restrict__ s, const float* __restrict__ gamma,
    const float* __restrict__ w_prev, const float* __restrict__ e,
    const float* __restrict__ a, float* __restrict__ newmem,
    float* __restrict__ r_out)
{
    __shared__ union {
        struct { float4 ks[32]; float invnk; } c;
        struct { float4 sd[256]; } w;
    } sh;
    __shared__ float red[8];
    __shared__ bool is_last;

    int bid = blockIdx.x;
    int b = bid >> 8;
    int j = bid & 255;
    int tid = threadIdx.x;
    int warp = tid >> 5, lane = tid & 31;

    if (j < 128) {
        // ================= cos phase =================
        if (tid < 32) {
            float4 k4 = reinterpret_cast<const float4*>(k + b * M)[tid];
            k4.x += EPS; k4.y += EPS; k4.z += EPS; k4.w += EPS;
            sh.c.ks[tid] = k4;
            float nk2 = k4.x * k4.x + k4.y * k4.y + k4.z * k4.z + k4.w * k4.w;
            #pragma unroll
            for (int t = 16; t > 0; t >>= 1)
                nk2 += __shfl_xor_sync(0xffffffffu, nk2, t);
            if (tid == 0) sh.c.invnk = 1.f / fmaxf(sqrtf(nk2), EPS_COS);
        }
        __syncthreads();

        int sub = lane >> 3, lane8 = lane & 7;   // 4 row-groups of 8 lanes
        int n0 = j * CROWS;
        float invnk = sh.c.invnk;

        #pragma unroll
        for (int iter = 0; iter < 2; ++iter) {
            int row = n0 + iter * 32 + warp * 4 + sub;
            const float4* mp = reinterpret_cast<const float4*>(
                mem + ((size_t)b * N + row) * M);

            float dot = 0.f, nm2 = 0.f;
            #pragma unroll
            for (int jj = 0; jj < 4; ++jj) {
                float4 m4 = __ldcs(mp + lane8 + jj * 8);
                float4 k4 = sh.c.ks[lane8 + jj * 8];
                float mx = m4.x + EPS, my = m4.y + EPS,
                      mz = m4.z + EPS, mw = m4.w + EPS;
                dot += mx * k4.x + my * k4.y + mz * k4.z + mw * k4.w;
                nm2 += mx * mx + my * my + mz * mz + mw * mw;
            }
            #pragma unroll
            for (int t = 4; t > 0; t >>= 1) {
                dot += __shfl_xor_sync(0xffffffffu, dot, t);
                nm2 += __shfl_xor_sync(0xffffffffu, nm2, t);
            }
            if (lane8 == 0) {
                float nm = fmaxf(sqrtf(nm2), EPS_COS);
                g_cos[(size_t)b * N + row] = dot * invnk / nm;
            }
        }

        // ---- ticket: last cos block of this batch runs the addr phase ----
        __threadfence();
        if (tid == 0) {
            unsigned int v = atomicAdd(&g_cnt_c[b], 1u);
            is_last = (v == 127u);
            if (is_last) g_cnt_c[b] = 0;   // self-reset for graph replay
        }
        __syncthreads();
        if (!is_last) return;

        // ================= addr phase (in-place in g_cos, L2-hot) =========
        float betav = beta[b], gv = g[b], gammav = gamma[b];
        float s0 = s[b * 3 + 0], s1 = s[b * 3 + 1], s2 = s[b * 3 + 2];
        float* cw = g_cos + (size_t)b * N;
        float* wo = g_w + (size_t)b * N;
        const float* wpv = w_prev + (size_t)b * N;

        // pass 1: ev = exp(beta*cos) (|beta*cos| <= 5, no max shift), sum
        float sum = 0.f;
        #pragma unroll
        for (int jj = 0; jj < N / 256; ++jj) {
            int i = tid + jj * 256;
            float ev = __expf(betav * cw[i]);
            cw[i] = ev;
            sum += ev;
        }
        #pragma unroll
        for (int t = 16; t > 0; t >>= 1)
            sum += __shfl_xor_sync(0xffffffffu, sum, t);
        if (lane == 0) red[warp] = sum;
        __syncthreads();
        float bsum = 0.f;
        #pragma unroll
        for (int w = 0; w < 8; ++w) bsum += red[w];
        float inv = 1.f / bsum;

        // pass 2: wg = g*wc + (1-g)*w_prev (in place)
        #pragma unroll
        for (int jj = 0; jj < N / 256; ++jj) {
            int i = tid + jj * 256;
            cw[i] = gv * (cw[i] * inv) + (1.f - gv) * wpv[i];
        }
        __syncthreads();

        // pass 3: circular shift + sharpen -> g_w, sum
        float sum2 = 0.f;
        #pragma unroll
        for (int jj = 0; jj < N / 256; ++jj) {
            int i = tid + jj * 256;
            int im1 = (i == 0) ? (N - 1) : (i - 1);
            int ip1 = (i == N - 1) ? 0 : (i + 1);
            float wh = s0 * cw[im1] + s1 * cw[i] + s2 * cw[ip1];
            float ww = __expf(gammav * __logf(wh));   // wh > 0 always
            wo[i] = ww;
            sum2 += ww;
        }
        #pragma unroll
        for (int t = 16; t > 0; t >>= 1)
            sum2 += __shfl_xor_sync(0xffffffffu, sum2, t);
        __syncthreads();
        if (lane == 0) red[warp] = sum2;
        __syncthreads();
        float bsum2 = 0.f;
        #pragma unroll
        for (int w = 0; w < 8; ++w) bsum2 += red[w];
        float inv2 = 1.f / (bsum2 + EPS);

        // pass 4: scale
        #pragma unroll
        for (int jj = 0; jj < N / 256; ++jj) {
            int i = tid + jj * 256;
            wo[i] *= inv2;
        }

        __threadfence();
        if (tid == 0) atomicExch(&g_flag[b], 1u);
        return;
    }

    // ================= write phase =================
    {
        int blk = j - 128;             // 0..127
        int m4 = tid & 31;             // float4 index along M
        int grp = tid >> 5;            // 8 row groups

        // wait for this batch's weights (producers have lower bids -> safe).
        // NO prefetch across the spin: keep regs low, slots cheap.
        if (tid == 0) {
            volatile unsigned int* fp = &g_flag[b];
            while (*fp == 0u) __nanosleep(64);
        }
        __syncthreads();
        __threadfence();   // acquire: order g_w reads after flag observation

        const float4 e4 = reinterpret_cast<const float4*>(e + b * M)[m4];
        const float4 a4 = reinterpret_cast<const float4*>(a + b * M)[m4];

        int n0 = blk * ROWS_PER_BLK;
        size_t base = ((size_t)b * N + n0) * M;
        const float4* mp = reinterpret_cast<const float4*>(mem + base);
        float4* op = reinterpret_cast<float4*>(newmem + base);
        const float* wp = g_w + (size_t)b * N + n0;

        float4 racc = make_float4(0.f, 0.f, 0.f, 0.f);
        #pragma unroll
        for (int it = 0; it < ROWS_PER_BLK / 8; ++it) {
            int row = it * 8 + grp;
            float wv = __ldg(wp + row);
            float4 mv = __ldcs(mp + row * 32 + m4);
            float4 o;
            o.x = mv.x * (1.f - wv * e4.x) + wv * a4.x;
            o.y = mv.y * (1.f - wv * e4.y) + wv * a4.y;
            o.z = mv.z * (1.f - wv * e4.z) + wv * a4.z;
            o.w = mv.w * (1.f - wv * e4.w) + wv * a4.w;
            __stcs(op + row * 32 + m4, o);
            racc.x += wv * mv.x;
            racc.y += wv * mv.y;
            racc.z += wv * mv.z;
            racc.w += wv * mv.w;
        }

        sh.w.sd[tid] = racc;
        __syncthreads();
        #pragma unroll
        for (int st = 4; st > 0; st >>= 1) {
            if (grp < st) {
                float4 o = sh.w.sd[tid + st * 32];
                sh.w.sd[tid].x += o.x; sh.w.sd[tid].y += o.y;
                sh.w.sd[tid].z += o.z; sh.w.sd[tid].w += o.w;
            }
            __syncthreads();
        }
        if (grp == 0) {
            reinterpret_cast<float4*>(
                g_pr + ((size_t)b * 128 + blk) * M)[m4] = sh.w.sd[tid];
        }

        // ticket: last write block of this batch reduces the partials
        __threadfence();
        if (tid == 0) {
            unsigned int v = atomicAdd(&g_cnt_w[b], 1u);
            is_last = (v == 127u);
            if (is_last) g_cnt_w[b] = 0;   // self-reset
        }
        __syncthreads();
        if (!is_last) return;

        float4 acc = make_float4(0.f, 0.f, 0.f, 0.f);
        const float4* pp = reinterpret_cast<const float4*>(
            g_pr + (size_t)b * 128 * M);
        #pragma unroll
        for (int jj = 0; jj < 16; ++jj) {
            float4 v = pp[(grp + jj * 8) * 32 + m4];
            acc.x += v.x; acc.y += v.y; acc.z += v.z; acc.w += v.w;
        }
        __syncthreads();
        sh.w.sd[tid] = acc;
        __syncthreads();
        #pragma unroll
        for (int st = 4; st > 0; st >>= 1) {
            if (grp < st) {
                float4 o = sh.w.sd[tid + st * 32];
                sh.w.sd[tid].x += o.x; sh.w.sd[tid].y += o.y;
                sh.w.sd[tid].z += o.z; sh.w.sd[tid].w += o.w;
            }
            __syncthreads();
        }
        if (grp == 0) {
            reinterpret_cast<float4*>(r_out + b * M)[m4] = sh.w.sd[tid];
        }
        // reset flag for next graph replay (all consumers already passed it)
        if (tid == 0) atomicExch(&g_flag[b], 0u);
    }
}

// ---------------- launch ----------------
extern "C" void kernel_launch(void* const* d_in, const int* in_sizes, int n_in,
                              void* d_out, int out_size) {
    const float* memory = (const float*)d_in[0];
    const float* k      = (const float*)d_in[1];
    const float* beta   = (const float*)d_in[2];
    const float* g      = (const float*)d_in[3];
    const float* s      = (const float*)d_in[4];
    const float* gamma  = (const float*)d_in[5];
    const float* w_prev = (const float*)d_in[6];
    const float* e      = (const float*)d_in[7];
    const float* a      = (const float*)d_in[8];

    float* r_out  = (float*)d_out;            // [B, M]
    float* nm_out = (float*)d_out + B * M;    // [B, N, M]

    // single batch-interleaved kernel: bid = b*256 + j
    ntm_kernel<<<B * 256, 256>>>(memory, k, beta, g, s, gamma,
                                 w_prev, e, a, nm_out, r_out);
}

// round 12
// speedup vs baseline: 2.2460x; 1.6986x over previous
#include <cuda_runtime.h>
#include <math.h>

#define B 64
#define N 8192
#define M 128
#define EPS 1e-16f
#define EPS_COS 1e-8f

// ---------------- scratch (no allocation allowed) ----------------
__device__ float g_ev[B * N];             // 2 MB: exp(beta*cos)
__device__ float g_es[B * 128];           // per-cos-block partial exp sums
__device__ float g_w[B * N];              // 2 MB: unnormalized sharpened weights
__device__ float g_inv2[B];               // final normalization factors
__device__ float g_pr[B * 64 * M];        // 2 MB: partial r [B][64][M]
__device__ unsigned int g_cnt_w[B];       // write-completion tickets

// ============ kernel 1: cos + exp + per-block partial sum ============
// grid (N/64, B), 256 threads. k-side hoisted, 8 lanes per row.
#define CROWS 64
__global__ __launch_bounds__(256) void cos_kernel(
    const float* __restrict__ mem, const float* __restrict__ k,
    const float* __restrict__ beta)
{
    __shared__ float4 ks[32];
    __shared__ float s_invnk;
    __shared__ float red[8];
    int b = blockIdx.y;
    int tid = threadIdx.x;
    int warp = tid >> 5, lane = tid & 31;

    if (tid < 32) {
        float4 k4 = reinterpret_cast<const float4*>(k + b * M)[tid];
        k4.x += EPS; k4.y += EPS; k4.z += EPS; k4.w += EPS;
        ks[tid] = k4;
        float nk2 = k4.x * k4.x + k4.y * k4.y + k4.z * k4.z + k4.w * k4.w;
        #pragma unroll
        for (int s = 16; s > 0; s >>= 1) nk2 += __shfl_xor_sync(0xffffffffu, nk2, s);
        if (tid == 0) s_invnk = 1.f / fmaxf(sqrtf(nk2), EPS_COS);
    }
    __syncthreads();

    int sub = lane >> 3, lane8 = lane & 7;   // 4 row-groups of 8 lanes
    int n0 = blockIdx.x * CROWS;
    float invnk = s_invnk;
    float betav = beta[b];

    float esum = 0.f;   // this thread's contribution to block exp-sum
    #pragma unroll
    for (int iter = 0; iter < 2; ++iter) {
        int row = n0 + iter * 32 + warp * 4 + sub;
        const float4* mp = reinterpret_cast<const float4*>(
            mem + ((size_t)b * N + row) * M);

        float dot = 0.f, nm2 = 0.f;
        #pragma unroll
        for (int j = 0; j < 4; ++j) {
            float4 m4 = __ldcs(mp + lane8 + j * 8);
            float4 k4 = ks[lane8 + j * 8];
            float mx = m4.x + EPS, my = m4.y + EPS, mz = m4.z + EPS, mw = m4.w + EPS;
            dot += mx * k4.x + my * k4.y + mz * k4.z + mw * k4.w;
            nm2 += mx * mx + my * my + mz * mz + mw * mw;
        }
        #pragma unroll
        for (int s = 4; s > 0; s >>= 1) {
            dot += __shfl_xor_sync(0xffffffffu, dot, s);
            nm2 += __shfl_xor_sync(0xffffffffu, nm2, s);
        }
        if (lane8 == 0) {
            float nm = fmaxf(sqrtf(nm2), EPS_COS);
            float cosv = dot * invnk / nm;
            // |beta*cos| <= 5 -> exp safe without max shift
            float ev = __expf(betav * cosv);
            g_ev[(size_t)b * N + row] = ev;
            esum += ev;
        }
    }

    // block-reduce esum (fixed order -> deterministic)
    #pragma unroll
    for (int s = 16; s > 0; s >>= 1)
        esum += __shfl_xor_sync(0xffffffffu, esum, s);
    if (lane == 0) red[warp] = esum;
    __syncthreads();
    if (tid == 0) {
        float bs = 0.f;
        #pragma unroll
        for (int w = 0; w < 8; ++w) bs += red[w];
        g_es[b * 128 + blockIdx.x] = bs;
    }
}

// ============ kernel 2: interpolation + shift + sharpen (no pass1/pass4) ====
// one block per batch, 1024 threads, 8 elems/thread, wg in shared
__global__ __launch_bounds__(1024) void addr_kernel(
    const float* __restrict__ g, const float* __restrict__ s,
    const float* __restrict__ gamma, const float* __restrict__ w_prev)
{
    __shared__ float sw[N];        // 32 KB
    __shared__ float red[32];
    int b = blockIdx.x;
    int tid = threadIdx.x;
    int lane = tid & 31, wid = tid >> 5;

    if (tid == 0) g_cnt_w[b] = 0;  // reset ticket for kernel 3

    float gv = g[b], gammav = gamma[b];
    float s0 = s[b * 3 + 0], s1 = s[b * 3 + 1], s2 = s[b * 3 + 2];

    // softmax denominator from the 128 per-block partials (fixed order)
    float ps = (tid < 128) ? g_es[b * 128 + tid] : 0.f;
    if (wid < 4) {
        #pragma unroll
        for (int t = 16; t > 0; t >>= 1) ps += __shfl_xor_sync(0xffffffffu, ps, t);
        if (lane == 0) red[wid] = ps;
    }
    __syncthreads();
    float bsum = red[0] + red[1] + red[2] + red[3];
    float inv = 1.f / bsum;

    // pass A: wg = g * (ev * inv) + (1-g) * w_prev  -> shared
    #pragma unroll
    for (int j = 0; j < N / 1024; ++j) {
        int i = tid + j * 1024;
        sw[i] = gv * (g_ev[(size_t)b * N + i] * inv)
              + (1.f - gv) * w_prev[(size_t)b * N + i];
    }
    __syncthreads();

    // pass B: circular shift + sharpen -> g_w (unnormalized), sum
    float wloc[N / 1024];
    float sum2 = 0.f;
    #pragma unroll
    for (int j = 0; j < N / 1024; ++j) {
        int i = tid + j * 1024;
        int im1 = (i == 0) ? (N - 1) : (i - 1);
        int ip1 = (i == N - 1) ? 0 : (i + 1);
        float wh = s0 * sw[im1] + s1 * sw[i] + s2 * sw[ip1];
        float ww = __expf(gammav * __logf(wh));   // wh > 0 always
        wloc[j] = ww;
        sum2 += ww;
    }
    #pragma unroll
    for (int t = 16; t > 0; t >>= 1) sum2 += __shfl_xor_sync(0xffffffffu, sum2, t);
    __syncthreads();
    if (lane == 0) red[wid] = sum2;
    __syncthreads();
    float bsum2 = 0.f;
    #pragma unroll
    for (int w = 0; w < 32; ++w) bsum2 += red[w];

    #pragma unroll
    for (int j = 0; j < N / 1024; ++j) {
        int i = tid + j * 1024;
        g_w[(size_t)b * N + i] = wloc[j];
    }
    if (tid == 0) g_inv2[b] = 1.f / (bsum2 + EPS);   // folded into kernel 3
}

// ============ kernel 3: new_mem write + fused r reduction ============
// grid (64, B), 256 threads; each block: 128 rows of one batch.
#define ROWS_PER_BLK 128
__global__ __launch_bounds__(256) void write_kernel(
    const float* __restrict__ mem, const float* __restrict__ e,
    const float* __restrict__ a, float* __restrict__ newmem,
    float* __restrict__ r_out)
{
    int b = blockIdx.y;
    int blk = blockIdx.x;              // 0..63
    int t = threadIdx.x;
    int m4 = t & 31;                   // float4 index along M
    int grp = t >> 5;                  // 8 row groups

    const float4 e4 = reinterpret_cast<const float4*>(e + b * M)[m4];
    const float4 a4 = reinterpret_cast<const float4*>(a + b * M)[m4];
    float inv2 = g_inv2[b];

    int n0 = blk * ROWS_PER_BLK;
    size_t base = ((size_t)b * N + n0) * M;
    const float4* mp = reinterpret_cast<const float4*>(mem + base);
    float4* op = reinterpret_cast<float4*>(newmem + base);
    const float* wp = g_w + (size_t)b * N + n0;

    float4 racc = make_float4(0.f, 0.f, 0.f, 0.f);
    #pragma unroll
    for (int it = 0; it < ROWS_PER_BLK / 8; ++it) {
        int row = it * 8 + grp;
        float wv = __ldg(wp + row) * inv2;     // folded normalization
        float4 mv = __ldcs(mp + row * 32 + m4);
        float4 o;
        o.x = mv.x * (1.f - wv * e4.x) + wv * a4.x;
        o.y = mv.y * (1.f - wv * e4.y) + wv * a4.y;
        o.z = mv.z * (1.f - wv * e4.z) + wv * a4.z;
        o.w = mv.w * (1.f - wv * e4.w) + wv * a4.w;
        __stcs(op + row * 32 + m4, o);
        racc.x += wv * mv.x;
        racc.y += wv * mv.y;
        racc.z += wv * mv.z;
        racc.w += wv * mv.w;
    }

    __shared__ float4 sd[256];
    __shared__ bool is_last;
    sd[t] = racc;
    __syncthreads();
    #pragma unroll
    for (int st = 4; st > 0; st >>= 1) {
        if (grp < st) {
            float4 o = sd[t + st * 32];
            sd[t].x += o.x; sd[t].y += o.y; sd[t].z += o.z; sd[t].w += o.w;
        }
        __syncthreads();
    }
    if (grp == 0) {
        reinterpret_cast<float4*>(g_pr + ((size_t)b * 64 + blk) * M)[m4] = sd[t];
    }

    // ticket: last block of this batch reduces the 64 partials (L2-hot)
    __threadfence();
    if (t == 0) {
        unsigned int v = atomicAdd(&g_cnt_w[b], 1u);
        is_last = (v == 63u);
    }
    __syncthreads();
    if (!is_last) return;

    float4 acc = make_float4(0.f, 0.f, 0.f, 0.f);
    const float4* pp = reinterpret_cast<const float4*>(g_pr + (size_t)b * 64 * M);
    #pragma unroll
    for (int j = 0; j < 8; ++j) {
        float4 v = pp[(grp + j * 8) * 32 + m4];
        acc.x += v.x; acc.y += v.y; acc.z += v.z; acc.w += v.w;
    }
    __syncthreads();
    sd[t] = acc;
    __syncthreads();
    #pragma unroll
    for (int st = 4; st > 0; st >>= 1) {
        if (grp < st) {
            float4 o = sd[t + st * 32];
            sd[t].x += o.x; sd[t].y += o.y; sd[t].z += o.z; sd[t].w += o.w;
        }
        __syncthreads();
    }
    if (grp == 0) {
        reinterpret_cast<float4*>(r_out + b * M)[m4] = sd[t];
    }
}

// ---------------- launch ----------------
extern "C" void kernel_launch(void* const* d_in, const int* in_sizes, int n_in,
                              void* d_out, int out_size) {
    const float* memory = (const float*)d_in[0];
    const float* k      = (const float*)d_in[1];
    const float* beta   = (const float*)d_in[2];
    const float* g      = (const float*)d_in[3];
    const float* s      = (const float*)d_in[4];
    const float* gamma  = (const float*)d_in[5];
    const float* w_prev = (const float*)d_in[6];
    const float* e      = (const float*)d_in[7];
    const float* a      = (const float*)d_in[8];

    float* r_out  = (float*)d_out;            // [B, M]
    float* nm_out = (float*)d_out + B * M;    // [B, N, M]

    // kernel 1: cos + exp + partial softmax sums
    dim3 grid1(N / CROWS, B);
    cos_kernel<<<grid1, 256>>>(memory, k, beta);

    // kernel 2: interpolation + shift + sharpen (resets write tickets)
    addr_kernel<<<B, 1024>>>(g, s, gamma, w_prev);

    // kernel 3: write + fused deterministic r reduction (normalization folded)
    dim3 grid3(N / ROWS_PER_BLK, B);
    write_kernel<<<grid3, 256>>>(memory, e, a, nm_out, r_out);
}

// round 13
// speedup vs baseline: 2.3579x; 1.0498x over previous
#include <cuda_runtime.h>
#include <math.h>

#define B 64
#define N 8192
#define M 128
#define EPS 1e-16f
#define EPS_COS 1e-8f

// ---------------- scratch (no allocation allowed) ----------------
__device__ float g_ev[B * N];             // 2 MB: exp(beta*cos)
__device__ float g_es[B * 1024];          // per-warp partial exp sums
__device__ float g_w[B * N];              // 2 MB: unnormalized sharpened weights
__device__ float g_inv2[B];               // final normalization factors
__device__ float g_pr[B * 64 * M];        // 2 MB: partial r [B][64][M]
__device__ unsigned int g_cnt_w[B];       // write-completion tickets

// ============ kernel 1: cos + exp + per-WARP partial sum (no end barrier) ===
// grid (N/64, B), 256 threads. k-side hoisted, 8 lanes per row.
#define CROWS 64
__global__ __launch_bounds__(256) void cos_kernel(
    const float* __restrict__ mem, const float* __restrict__ k,
    const float* __restrict__ beta)
{
    __shared__ float4 ks[32];
    __shared__ float s_invnk;
    int b = blockIdx.y;
    int tid = threadIdx.x;
    int warp = tid >> 5, lane = tid & 31;

    if (tid < 32) {
        float4 k4 = reinterpret_cast<const float4*>(k + b * M)[tid];
        k4.x += EPS; k4.y += EPS; k4.z += EPS; k4.w += EPS;
        ks[tid] = k4;
        float nk2 = k4.x * k4.x + k4.y * k4.y + k4.z * k4.z + k4.w * k4.w;
        #pragma unroll
        for (int s = 16; s > 0; s >>= 1) nk2 += __shfl_xor_sync(0xffffffffu, nk2, s);
        if (tid == 0) s_invnk = 1.f / fmaxf(sqrtf(nk2), EPS_COS);
    }
    __syncthreads();

    int sub = lane >> 3, lane8 = lane & 7;   // 4 row-groups of 8 lanes
    int n0 = blockIdx.x * CROWS;
    float invnk = s_invnk;
    float betav = beta[b];

    float esum = 0.f;   // nonzero only at lanes 0,8,16,24
    #pragma unroll
    for (int iter = 0; iter < 2; ++iter) {
        int row = n0 + iter * 32 + warp * 4 + sub;
        const float4* mp = reinterpret_cast<const float4*>(
            mem + ((size_t)b * N + row) * M);

        float dot = 0.f, nm2 = 0.f;
        #pragma unroll
        for (int j = 0; j < 4; ++j) {
            float4 m4 = __ldcs(mp + lane8 + j * 8);
            float4 k4 = ks[lane8 + j * 8];
            float mx = m4.x + EPS, my = m4.y + EPS, mz = m4.z + EPS, mw = m4.w + EPS;
            dot += mx * k4.x + my * k4.y + mz * k4.z + mw * k4.w;
            nm2 += mx * mx + my * my + mz * mz + mw * mw;
        }
        #pragma unroll
        for (int s = 4; s > 0; s >>= 1) {
            dot += __shfl_xor_sync(0xffffffffu, dot, s);
            nm2 += __shfl_xor_sync(0xffffffffu, nm2, s);
        }
        if (lane8 == 0) {
            float nm = fmaxf(sqrtf(nm2), EPS_COS);
            float cosv = dot * invnk / nm;
            // |beta*cos| <= 5 -> exp safe without max shift
            float ev = __expf(betav * cosv);
            g_ev[(size_t)b * N + row] = ev;
            esum += ev;
        }
    }

    // fold lanes {0,8,16,24} -> lane 0 (fixed order, 2 shuffles, no barrier)
    esum += __shfl_xor_sync(0xffffffffu, esum, 8);
    esum += __shfl_xor_sync(0xffffffffu, esum, 16);
    if (lane == 0) g_es[b * 1024 + blockIdx.x * 8 + warp] = esum;
}

// ============ kernel 2: interpolation + shift + sharpen ============
// one block per batch, 1024 threads, 8 elems/thread, wg in shared
__global__ __launch_bounds__(1024) void addr_kernel(
    const float* __restrict__ g, const float* __restrict__ s,
    const float* __restrict__ gamma, const float* __restrict__ w_prev)
{
    __shared__ float sw[N];        // 32 KB
    __shared__ float red[32];
    int b = blockIdx.x;
    int tid = threadIdx.x;
    int lane = tid & 31, wid = tid >> 5;

    if (tid == 0) g_cnt_w[b] = 0;  // reset ticket for kernel 3

    float gv = g[b], gammav = gamma[b];
    float s0 = s[b * 3 + 0], s1 = s[b * 3 + 1], s2 = s[b * 3 + 2];

    // softmax denominator from 1024 per-warp partials (fixed-order tree)
    float ps = g_es[b * 1024 + tid];
    #pragma unroll
    for (int t = 16; t > 0; t >>= 1) ps += __shfl_xor_sync(0xffffffffu, ps, t);
    if (lane == 0) red[wid] = ps;
    __syncthreads();
    float bsum = 0.f;
    #pragma unroll
    for (int w = 0; w < 32; ++w) bsum += red[w];
    float inv = 1.f / bsum;

    // pass A: wg = g * (ev * inv) + (1-g) * w_prev  -> shared
    #pragma unroll
    for (int j = 0; j < N / 1024; ++j) {
        int i = tid + j * 1024;
        sw[i] = gv * (g_ev[(size_t)b * N + i] * inv)
              + (1.f - gv) * w_prev[(size_t)b * N + i];
    }
    __syncthreads();

    // pass B: circular shift + sharpen -> g_w (unnormalized), sum
    float wloc[N / 1024];
    float sum2 = 0.f;
    #pragma unroll
    for (int j = 0; j < N / 1024; ++j) {
        int i = tid + j * 1024;
        int im1 = (i == 0) ? (N - 1) : (i - 1);
        int ip1 = (i == N - 1) ? 0 : (i + 1);
        float wh = s0 * sw[im1] + s1 * sw[i] + s2 * sw[ip1];
        float ww = __expf(gammav * __logf(wh));   // wh > 0 always
        wloc[j] = ww;
        sum2 += ww;
    }
    #pragma unroll
    for (int t = 16; t > 0; t >>= 1) sum2 += __shfl_xor_sync(0xffffffffu, sum2, t);
    __syncthreads();
    if (lane == 0) red[wid] = sum2;
    __syncthreads();
    float bsum2 = 0.f;
    #pragma unroll
    for (int w = 0; w < 32; ++w) bsum2 += red[w];

    #pragma unroll
    for (int j = 0; j < N / 1024; ++j) {
        int i = tid + j * 1024;
        g_w[(size_t)b * N + i] = wloc[j];
    }
    if (tid == 0) g_inv2[b] = 1.f / (bsum2 + EPS);   // folded into kernel 3
}

// ============ kernel 3: new_mem write + fused r reduction ============
// grid (64, B), 256 threads; each block: 128 rows of one batch.
// Loads batched in groups of 4 (MLP) before the 4 stores.
#define ROWS_PER_BLK 128
__global__ __launch_bounds__(256) void write_kernel(
    const float* __restrict__ mem, const float* __restrict__ e,
    const float* __restrict__ a, float* __restrict__ newmem,
    float* __restrict__ r_out)
{
    int b = blockIdx.y;
    int blk = blockIdx.x;              // 0..63
    int t = threadIdx.x;
    int m4 = t & 31;                   // float4 index along M
    int grp = t >> 5;                  // 8 row groups

    const float4 e4 = reinterpret_cast<const float4*>(e + b * M)[m4];
    const float4 a4 = reinterpret_cast<const float4*>(a + b * M)[m4];
    float inv2 = g_inv2[b];

    int n0 = blk * ROWS_PER_BLK;
    size_t base = ((size_t)b * N + n0) * M;
    const float4* mp = reinterpret_cast<const float4*>(mem + base);
    float4* op = reinterpret_cast<float4*>(newmem + base);
    const float* wp = g_w + (size_t)b * N + n0;

    float4 racc = make_float4(0.f, 0.f, 0.f, 0.f);
    #pragma unroll
    for (int it4 = 0; it4 < ROWS_PER_BLK / 8; it4 += 4) {
        float4 mv[4];
        float wv[4];
        // batch 4 independent loads first (MLP, fewer rd/wr turnarounds)
        #pragma unroll
        for (int u = 0; u < 4; ++u) {
            int row = (it4 + u) * 8 + grp;
            mv[u] = __ldcs(mp + row * 32 + m4);
            wv[u] = __ldg(wp + row) * inv2;    // folded normalization
        }
        #pragma unroll
        for (int u = 0; u < 4; ++u) {
            int row = (it4 + u) * 8 + grp;
            float4 m = mv[u];
            float w = wv[u];
            float4 o;
            o.x = m.x * (1.f - w * e4.x) + w * a4.x;
            o.y = m.y * (1.f - w * e4.y) + w * a4.y;
            o.z = m.z * (1.f - w * e4.z) + w * a4.z;
            o.w = m.w * (1.f - w * e4.w) + w * a4.w;
            __stcs(op + row * 32 + m4, o);
            racc.x += w * m.x;
            racc.y += w * m.y;
            racc.z += w * m.z;
            racc.w += w * m.w;
        }
    }

    __shared__ float4 sd[256];
    __shared__ bool is_last;
    sd[t] = racc;
    __syncthreads();
    #pragma unroll
    for (int st = 4; st > 0; st >>= 1) {
        if (grp < st) {
            float4 o = sd[t + st * 32];
            sd[t].x += o.x; sd[t].y += o.y; sd[t].z += o.z; sd[t].w += o.w;
        }
        __syncthreads();
    }
    if (grp == 0) {
        reinterpret_cast<float4*>(g_pr + ((size_t)b * 64 + blk) * M)[m4] = sd[t];
    }

    // ticket: last block of this batch reduces the 64 partials (L2-hot)
    __threadfence();
    if (t == 0) {
        unsigned int v = atomicAdd(&g_cnt_w[b], 1u);
        is_last = (v == 63u);
    }
    __syncthreads();
    if (!is_last) return;

    float4 acc = make_float4(0.f, 0.f, 0.f, 0.f);
    const float4* pp = reinterpret_cast<const float4*>(g_pr + (size_t)b * 64 * M);
    #pragma unroll
    for (int j = 0; j < 8; ++j) {
        float4 v = pp[(grp + j * 8) * 32 + m4];
        acc.x += v.x; acc.y += v.y; acc.z += v.z; acc.w += v.w;
    }
    __syncthreads();
    sd[t] = acc;
    __syncthreads();
    #pragma unroll
    for (int st = 4; st > 0; st >>= 1) {
        if (grp < st) {
            float4 o = sd[t + st * 32];
            sd[t].x += o.x; sd[t].y += o.y; sd[t].z += o.z; sd[t].w += o.w;
        }
        __syncthreads();
    }
    if (grp == 0) {
        reinterpret_cast<float4*>(r_out + b * M)[m4] = sd[t];
    }
}

// ---------------- launch ----------------
extern "C" void kernel_launch(void* const* d_in, const int* in_sizes, int n_in,
                              void* d_out, int out_size) {
    const float* memory = (const float*)d_in[0];
    const float* k      = (const float*)d_in[1];
    const float* beta   = (const float*)d_in[2];
    const float* g      = (const float*)d_in[3];
    const float* s      = (const float*)d_in[4];
    const float* gamma  = (const float*)d_in[5];
    const float* w_prev = (const float*)d_in[6];
    const float* e      = (const float*)d_in[7];
    const float* a      = (const float*)d_in[8];

    float* r_out  = (float*)d_out;            // [B, M]
    float* nm_out = (float*)d_out + B * M;    // [B, N, M]

    // kernel 1: cos + exp + per-warp partial softmax sums
    dim3 grid1(N / CROWS, B);
    cos_kernel<<<grid1, 256>>>(memory, k, beta);

    // kernel 2: interpolation + shift + sharpen (resets write tickets)
    addr_kernel<<<B, 1024>>>(g, s, gamma, w_prev);

    // kernel 3: write + fused deterministic r reduction (normalization folded)
    dim3 grid3(N / ROWS_PER_BLK, B);
    write_kernel<<<grid3, 256>>>(memory, e, a, nm_out, r_out);
}